// round 9
// baseline (speedup 1.0000x reference)
#include <cuda_runtime.h>

// D2Q9 LBM single step — element-parallel collide into smem (coalesced),
// then smem gather + bounce-back + macro lift.
//   f    [2048,2048,9]  f32
//   rho  [2048,2048]    f32
//   u    [2048,2048,2]  f32 (float2)
//   mask [2048,2048]    bool, dtype unknown (u8/i32/f32) -> runtime detection
//   out  [2048,2048,12] f32  (f_new[9], rho_new, ux, uy)
//
// jnp.roll(a, shift=e) => new[x,y] = old[x-ex, y-ey] (periodic &2047).

#define NXg 2048
#define NYg 2048
#define WRAP(v) ((v) & 2047)

#define TW 64            // tile width  (y, contiguous)
#define TH 8             // tile height (x)
#define HW (TW + 2)      // 66
#define HH (TH + 2)      // 10
#define HCELLS (HW * HH) // 660
#define HELEMS (HCELLS * 9) // 5940

// ---- mask dtype detection (device globals zero-init; atomicOr idempotent) ----
__device__ unsigned int g_byte_flags[4];

__global__ void detect_mask_kernel(const uint4* __restrict__ mask_v) {
    // Scan first 256 KB (smallest candidate buffer is 4 MB; ~65k cells seen).
    const int nvec = (256 * 1024) / 16;
    unsigned int loc0 = 0, loc1 = 0, loc2 = 0, loc3 = 0;
    for (int i = blockIdx.x * blockDim.x + threadIdx.x; i < nvec;
         i += gridDim.x * blockDim.x) {
        uint4 v = mask_v[i];
        unsigned int w = v.x | v.y | v.z | v.w;
        loc0 |= (w & 0x000000FFu);
        loc1 |= (w & 0x0000FF00u);
        loc2 |= (w & 0x00FF0000u);
        loc3 |= (w & 0xFF000000u);
    }
    if (loc0) atomicOr(&g_byte_flags[0], 1u);
    if (loc1) atomicOr(&g_byte_flags[1], 1u);
    if (loc2) atomicOr(&g_byte_flags[2], 1u);
    if (loc3) atomicOr(&g_byte_flags[3], 1u);
}

__global__ __launch_bounds__(256, 4)
void lbm_step_kernel(const float*  __restrict__ f,
                     const float*  __restrict__ rho,
                     const float2* __restrict__ u,
                     const void*   __restrict__ mask,
                     float* __restrict__ out)
{
    __shared__ float fs[HELEMS];   // f_star for tile+halo, flat [cell][i], 23.8 KB

    const int tid = threadIdx.x;
    const int Y0  = blockIdx.x * TW;
    const int X0  = blockIdx.y * TH;

    // Resolve mask dtype from detection flags (uniform loads, L2 broadcast)
    const bool b0  = g_byte_flags[0] != 0;
    const bool b1  = g_byte_flags[1] != 0;
    const bool b23 = (g_byte_flags[2] | g_byte_flags[3]) != 0;
    int mode;
    if (b1 || (b0 && b23)) mode = 0;       // 1-byte mask
    else if (b0)           mode = 1;       // int32
    else if (b23)          mode = 2;       // float32
    else                   mode = 0;       // no solids in window: any read works

    // Early mask loads for this thread's 2 output cells (latency hidden by phase A)
    const int ly  = tid & (TW - 1);        // 0..63
    const int lx0 = tid >> 6;              // 0..3 (second cell at lx0+4)
    bool solid[2];
    #pragma unroll
    for (int cp = 0; cp < 2; cp++) {
        const unsigned cell = (unsigned)(X0 + lx0 + 4 * cp) * NYg + (Y0 + ly);
        if (mode == 0)      solid[cp] = ((const unsigned char*)mask)[cell] != 0;
        else if (mode == 1) solid[cp] = ((const int*)mask)[cell] != 0;
        else                solid[cp] = ((const float*)mask)[cell] != 0.0f;
    }

    const float INV_TAU = 1.0f / 0.6f;

    // ---- Phase A: element-parallel collide into smem (coalesced f loads) ----
    // ex = +1 at i in {1,5,8} (0x122), -1 at {3,6,7} (0x0C8)
    // ey = +1 at i in {2,5,6} (0x064), -1 at {4,7,8} (0x190)
    #pragma unroll 4
    for (int n = tid; n < HELEMS; n += 256) {
        const unsigned c  = (unsigned)n / 9u;
        const unsigned i  = (unsigned)n - c * 9u;
        const unsigned h  = c / (unsigned)HW;
        const unsigned hy = c - h * (unsigned)HW;
        const int gx = WRAP(X0 + (int)h - 1);
        const int gy = WRAP(Y0 + (int)hy - 1);
        const unsigned gc = (unsigned)gx * NYg + gy;

        const float  fv = f[gc * 9u + i];
        const float  r  = rho[gc];
        const float2 uv = u[gc];

        const float ex = (float)((0x122u >> i) & 1u) - (float)((0x0C8u >> i) & 1u);
        const float ey = (float)((0x064u >> i) & 1u) - (float)((0x190u >> i) & 1u);
        const float w  = (i == 0u) ? (4.0f / 9.0f)
                                   : ((i < 5u) ? (1.0f / 9.0f) : (1.0f / 36.0f));

        const float eu  = ex * uv.x + ey * uv.y;
        const float usq = uv.x * uv.x + uv.y * uv.y;
        const float feq = w * r * (1.0f + 3.0f * eu + 4.5f * eu * eu - 1.5f * usq);
        fs[n] = fv - (fv - feq) * INV_TAU;
    }
    __syncthreads();

    // ---- Phase B: smem gather + bounce-back + macro lift + direct stores ----
    const int   EXq[9]  = {0, 1, 0, -1,  0, 1, -1, -1,  1};
    const int   EYq[9]  = {0, 0, 1,  0, -1, 1,  1, -1, -1};
    const int   OPPq[9] = {0, 3, 4, 1, 2, 7, 8, 5, 6};

    #pragma unroll
    for (int cp = 0; cp < 2; cp++) {
        const int lx = lx0 + 4 * cp;
        const unsigned cell = (unsigned)(X0 + lx) * NYg + (Y0 + ly);

        float fn[9];
        if (solid[cp]) {
            const int base = ((lx + 1) * HW + (ly + 1)) * 9;
            #pragma unroll
            for (int i = 0; i < 9; i++) fn[i] = fs[base + OPPq[i]];
        } else {
            #pragma unroll
            for (int i = 0; i < 9; i++)
                fn[i] = fs[((lx + 1 - EXq[i]) * HW + (ly + 1 - EYq[i])) * 9 + i];
        }

        float rn = 0.0f;
        #pragma unroll
        for (int i = 0; i < 9; i++) rn += fn[i];
        const float uxn = (fn[1] - fn[3]) + (fn[5] - fn[6]) + (fn[8] - fn[7]);
        const float uyn = (fn[2] - fn[4]) + (fn[5] + fn[6]) - (fn[7] + fn[8]);
        const float inv_rn = 1.0f / rn;

        float4* op = reinterpret_cast<float4*>(out + (size_t)cell * 12);
        op[0] = make_float4(fn[0], fn[1], fn[2], fn[3]);
        op[1] = make_float4(fn[4], fn[5], fn[6], fn[7]);
        op[2] = make_float4(fn[8], rn, uxn * inv_rn, uyn * inv_rn);
    }
}

extern "C" void kernel_launch(void* const* d_in, const int* in_sizes, int n_in,
                              void* d_out, int out_size)
{
    const float*  f    = (const float*)d_in[0];
    const float*  rho  = (const float*)d_in[1];
    const float2* u    = (const float2*)d_in[2];
    const void*   mask = d_in[3];
    float*        out  = (float*)d_out;

    detect_mask_kernel<<<32, 256>>>((const uint4*)mask);

    dim3 block(256);
    dim3 grid(NYg / TW, NXg / TH);   // 32 x 256 = 8192 CTAs
    lbm_step_kernel<<<grid, block>>>(f, rho, u, mask, out);
}